// round 3
// baseline (speedup 1.0000x reference)
#include <cuda_runtime.h>
#include <math.h>

// Problem constants
#define N_B     32
#define C_DIM   384
#define HW      3136        // 56*56
#define M_DIM   8
#define D_MODEL 768
#define E_DIM   768         // 2*C

#define TILE_P    56        // pixels per CTA
#define NTH       448       // threads per CTA
#define KV_CTAS   48        // CTAs per batch that compute a KV slice
#define E_PER_CTA 16        // e-values per KV slice (48*16 = 768)

// ---------------- device scratch (allowed: __device__ globals) -----------------
__device__ float    g_kv[N_B * M_DIM * E_DIM];     // [n][m][e]
__device__ unsigned g_flag[N_B * KV_CTAS];         // single-writer flags

// ---------------- smem layout (floats) -----------------------------------------
#define XS_STRIDE 57                               // 56 px + 1 pad (bank spread)
#define OFF_KS   (C_DIM * XS_STRIDE)               // 21888
#define OFF_VS   (OFF_KS + M_DIM * C_DIM)          // 24960
#define OFF_AT   (OFF_VS + M_DIM * C_DIM)          // 28032
#define SM_FLOATS (OFF_AT + TILE_P * 8)            // 28480
#define SM_BYTES  (SM_FLOATS * 4)                  // 113920 B -> 2 CTAs/SM

__global__ __launch_bounds__(NTH, 2) void fused_kernel(
    const float* __restrict__ x,
    const float* __restrict__ gf,
    const float* __restrict__ W,
    const float* __restrict__ bias,
    float* __restrict__ out)
{
    extern __shared__ float sm[];
    float* xs   = sm;                 // [c][p] stride 57
    float* Ks   = sm + OFF_KS;        // [k][c]
    float* Vs   = sm + OFF_VS;        // [k][c]
    float* attn = sm + OFF_AT;        // [p][k]

    const int tid = threadIdx.x;
    const int bx  = blockIdx.x;       // tile id (also KV slice id if <48)
    const int n   = blockIdx.y;
    const int p0  = bx * TILE_P;

    // ================= KV slice: clip(gf[n] @ W^T + b) for 16 e-values =========
    // threads 0..127: tid = el*8 + m ; warp: 4 e-rows (W broadcast to 8 lanes)
    if (bx < KV_CTAS && tid < 128) {
        const int m  = tid & 7;
        const int el = tid >> 3;
        const int e  = bx * E_PER_CTA + el;
        const float4* w4 = (const float4*)(W  + (size_t)e * D_MODEL);
        const float4* g4 = (const float4*)(gf + ((size_t)n * M_DIM + m) * D_MODEL);
        float4 a = make_float4(0.f, 0.f, 0.f, 0.f);
        #pragma unroll 4
        for (int d = 0; d < D_MODEL / 4; d++) {
            float4 wv = w4[d];
            float4 gv = g4[d];
            a.x += wv.x * gv.x; a.y += wv.y * gv.y;
            a.z += wv.z * gv.z; a.w += wv.w * gv.w;
        }
        float v = a.x + a.y + a.z + a.w + bias[e];
        v = fminf(fmaxf(v, 0.f), 6.f);
        g_kv[((size_t)n * M_DIM + m) * E_DIM + e] = v;
        __threadfence();
        asm volatile("bar.sync 1, 128;" ::: "memory");   // warps 0-3 only
        if (tid == 0) atomicExch(&g_flag[n * KV_CTAS + bx], 1u);
    }

    // ================= x tile load: 384 ch x 56 px, float4 coalesced ===========
    {
        const float* xb = x + (size_t)n * C_DIM * HW + p0;
        #pragma unroll
        for (int t = 0; t < 12; t++) {                  // 5376 float4 / 448
            int i = tid + t * NTH;
            int c = i / 14;                             // 14 float4 per channel row
            int j = i - c * 14;
            float4 v = *(const float4*)(xb + (size_t)c * HW + j * 4);
            float* d = &xs[c * XS_STRIDE + j * 4];
            d[0] = v.x; d[1] = v.y; d[2] = v.z; d[3] = v.w;
        }
    }

    // ================= wait for this batch's KV slices =========================
    if (tid < KV_CTAS) {
        while (atomicAdd(&g_flag[n * KV_CTAS + tid], 0u) == 0u) __nanosleep(64);
    }
    __syncthreads();
    __threadfence();      // acquire: make g_kv writes visible to every thread

    // ---- stage K,V into smem ----
    {
        const float4* kv4 = (const float4*)(g_kv + (size_t)n * (M_DIM * E_DIM));
        for (int i = tid; i < (M_DIM * E_DIM) / 4; i += NTH) {
            int m = i / 192;
            int j = i - m * 192;
            float4 v = kv4[i];
            int e = j * 4;
            if (e < C_DIM) *(float4*)&Ks[m * C_DIM + e] = v;
            else           *(float4*)&Vs[m * C_DIM + (e - C_DIM)] = v;
        }
    }
    __syncthreads();

    // ================= phase 1: scores, 8-way channel split in-warp ============
    // tid = p*8 + q : lane group of 8 holds pixel p, split q handles c ≡ q (mod 8)
    {
        const int q = tid & 7;
        const int p = tid >> 3;

        float acc[8];
        #pragma unroll
        for (int k = 0; k < 8; k++) acc[k] = 0.f;

        #pragma unroll 4
        for (int cc = 0; cc < 48; cc++) {
            int c = cc * 8 + q;
            float xv = xs[c * XS_STRIDE + p];
            #pragma unroll
            for (int k = 0; k < 8; k++)
                acc[k] += xv * Ks[k * C_DIM + c];
        }

        // butterfly-reduce across the 8 splits (within warp)
        #pragma unroll
        for (int off = 1; off < 8; off <<= 1) {
            #pragma unroll
            for (int k = 0; k < 8; k++)
                acc[k] += __shfl_xor_sync(0xffffffffu, acc[k], off);
        }

        // softmax over k=8 (all lanes compute; lane q==0 writes)
        float mx = acc[0];
        #pragma unroll
        for (int k = 1; k < 8; k++) mx = fmaxf(mx, acc[k]);
        float sum = 0.f;
        #pragma unroll
        for (int k = 0; k < 8; k++) { acc[k] = __expf(acc[k] - mx); sum += acc[k]; }
        float inv = 1.0f / sum;
        if (q == 0) {
            float* ap = &attn[p * 8];
            *(float4*)(ap + 0) = make_float4(acc[0]*inv, acc[1]*inv, acc[2]*inv, acc[3]*inv);
            *(float4*)(ap + 4) = make_float4(acc[4]*inv, acc[5]*inv, acc[6]*inv, acc[7]*inv);
        }
    }
    __syncthreads();

    // ================= phase 2: out = x + attn @ V =============================
    // remap: tid -> (q2 = channel-octant of 48ch, p2 = pixel) ; coalesced stores
    {
        const int q2 = tid / TILE_P;
        const int p2 = tid - q2 * TILE_P;

        float a[8];
        {
            const float* ap = &attn[p2 * 8];
            float4 u0 = *(const float4*)(ap + 0);
            float4 u1 = *(const float4*)(ap + 4);
            a[0]=u0.x; a[1]=u0.y; a[2]=u0.z; a[3]=u0.w;
            a[4]=u1.x; a[5]=u1.y; a[6]=u1.z; a[7]=u1.w;
        }

        float* op = out + (size_t)n * C_DIM * HW + p0 + p2;
        const int cbase = q2 * 48;
        #pragma unroll 2
        for (int i = 0; i < 48; i += 4) {
            int c = cbase + i;
            float o0 = xs[(c + 0) * XS_STRIDE + p2];
            float o1 = xs[(c + 1) * XS_STRIDE + p2];
            float o2 = xs[(c + 2) * XS_STRIDE + p2];
            float o3 = xs[(c + 3) * XS_STRIDE + p2];
            #pragma unroll
            for (int k = 0; k < 8; k++) {
                float4 vv = *(const float4*)&Vs[k * C_DIM + c];
                o0 += a[k] * vv.x; o1 += a[k] * vv.y;
                o2 += a[k] * vv.z; o3 += a[k] * vv.w;
            }
            op[(size_t)(c + 0) * HW] = o0;
            op[(size_t)(c + 1) * HW] = o1;
            op[(size_t)(c + 2) * HW] = o2;
            op[(size_t)(c + 3) * HW] = o3;
        }
    }
}

// ================= launch ======================================================
extern "C" void kernel_launch(void* const* d_in, const int* in_sizes, int n_in,
                              void* d_out, int out_size)
{
    const float* x  = (const float*)d_in[0];
    const float* gf = (const float*)d_in[1];
    const float* W  = (const float*)d_in[2];
    const float* b  = (const float*)d_in[3];
    float* out = (float*)d_out;

    cudaFuncSetAttribute(fused_kernel, cudaFuncAttributeMaxDynamicSharedMemorySize, SM_BYTES);
    fused_kernel<<<dim3(HW / TILE_P, N_B), NTH, SM_BYTES>>>(x, gf, W, b, out);
}

// round 4
// speedup vs baseline: 1.1805x; 1.1805x over previous
#include <cuda_runtime.h>
#include <math.h>

// Problem constants
#define N_B     32
#define C_DIM   384
#define HW      3136        // 56*56
#define M_DIM   8
#define D_MODEL 768
#define E_DIM   768         // 2*C
#define KV_N    (M_DIM * E_DIM)   // 6144 per batch

// ---------------- device scratch -----------------------------------------------
#define NSPLIT 4
__device__ __align__(16) float g_kvp[NSPLIT * N_B * M_DIM * E_DIM]; // raw partials
__device__ __align__(16) float g_kv [N_B * M_DIM * E_DIM];          // clipped KV

// ================= Kernel 1: split-K GEMM partials =============================
#define BM 32
#define BN 64
#define BK 32
#define DSPL (D_MODEL / NSPLIT)   // 192

__global__ __launch_bounds__(256) void kvp_kernel(
    const float* __restrict__ gf,
    const float* __restrict__ W)
{
    __shared__ float As[BK][BM + 2];
    __shared__ float Bs[BK][BN + 4];

    const int tid = threadIdx.x;
    const int tx  = tid & 15;
    const int ty  = tid >> 4;
    const int eb  = blockIdx.x * BN;
    const int rb  = blockIdx.y * BM;
    const int s   = blockIdx.z;

    float acc[2][4];
    #pragma unroll
    for (int i = 0; i < 2; i++)
        #pragma unroll
        for (int j = 0; j < 4; j++) acc[i][j] = 0.f;

    for (int kb = s * DSPL; kb < (s + 1) * DSPL; kb += BK) {
        #pragma unroll
        for (int i = 0; i < 4; i++) {
            int idx = tid + i * 256;
            int r  = idx >> 5;
            int kk = idx & 31;
            As[kk][r] = gf[(size_t)(rb + r) * D_MODEL + kb + kk];
        }
        #pragma unroll
        for (int i = 0; i < 8; i++) {
            int idx = tid + i * 256;
            int e  = idx >> 5;
            int kk = idx & 31;
            Bs[kk][e] = W[(size_t)(eb + e) * D_MODEL + kb + kk];
        }
        __syncthreads();

        #pragma unroll
        for (int kk = 0; kk < BK; kk++) {
            float2 av = *(const float2*)&As[kk][ty * 2];
            float4 bv = *(const float4*)&Bs[kk][tx * 4];
            acc[0][0] += av.x * bv.x; acc[0][1] += av.x * bv.y;
            acc[0][2] += av.x * bv.z; acc[0][3] += av.x * bv.w;
            acc[1][0] += av.y * bv.x; acc[1][1] += av.y * bv.y;
            acc[1][2] += av.y * bv.z; acc[1][3] += av.y * bv.w;
        }
        __syncthreads();
    }

    float* dst = g_kvp + (size_t)s * (N_B * KV_N);
    #pragma unroll
    for (int r = 0; r < 2; r++) {
        float4 o = make_float4(acc[r][0], acc[r][1], acc[r][2], acc[r][3]);
        *(float4*)&dst[(size_t)(rb + ty * 2 + r) * E_DIM + eb + tx * 4] = o;
    }
}

// ================= Kernel 1b: combine partials + bias + clip ===================
__global__ __launch_bounds__(512) void kv_combine_kernel(const float* __restrict__ bias)
{
    const int idx = blockIdx.x * 512 + threadIdx.x;   // one float4 each; 49152 total
    const float4* p = (const float4*)g_kvp;
    float4 v0 = p[idx];
    float4 v1 = p[idx + 49152];
    float4 v2 = p[idx + 2 * 49152];
    float4 v3 = p[idx + 3 * 49152];
    float4 bb = ((const float4*)bias)[idx % (E_DIM / 4)];
    float4 o;
    o.x = fminf(fmaxf(v0.x + v1.x + v2.x + v3.x + bb.x, 0.f), 6.f);
    o.y = fminf(fmaxf(v0.y + v1.y + v2.y + v3.y + bb.y, 0.f), 6.f);
    o.z = fminf(fmaxf(v0.z + v1.z + v2.z + v3.z + bb.z, 0.f), 6.f);
    o.w = fminf(fmaxf(v0.w + v1.w + v2.w + v3.w + bb.w, 0.f), 6.f);
    ((float4*)g_kv)[idx] = o;
}

// ================= Kernel 2: attention + residual ==============================
// Tile = 56 pixels x 384 channels in smem (one HBM read of x). K/V via __ldg (L1-hot).
// Phase 1: tid = p*8+q, split q handles channels [48q, 48q+48); butterfly reduce.
// Phase 2: tid = q2*56+p2, coalesced stores.
#define TILE_P  56
#define NTH     448
#define XQ_STR  2692                 // 48*56 + 4  (=> 4 mod 32: conflict-free)
#define OFF_AT  (8 * XQ_STR)         // 21536
#define SM_FLOATS (OFF_AT + TILE_P * 8)   // 21984
#define SM_BYTES  (SM_FLOATS * 4)         // 87936 -> 2 CTAs/SM

__global__ __launch_bounds__(NTH, 2) void attn_kernel(
    const float* __restrict__ x,
    float* __restrict__ out)
{
    extern __shared__ float sm[];
    float* xs   = sm;              // [q][i][p]: q*2692 + i*56 + p
    float* attn = sm + OFF_AT;     // [p][k]

    const int tid = threadIdx.x;
    const int n   = blockIdx.y;
    const int p0  = blockIdx.x * TILE_P;

    const float* kvb = g_kv + (size_t)n * KV_N;

    // ---- x tile load: 384 ch x 56 px (5376 float4, 12 per thread) ----
    {
        const float* xb = x + (size_t)n * C_DIM * HW + p0;
        #pragma unroll
        for (int t = 0; t < 12; t++) {
            int i = tid + t * NTH;
            int c = i / 14;                  // 14 float4 per channel row
            int j = i - c * 14;
            float4 v = *(const float4*)(xb + (size_t)c * HW + j * 4);
            int q  = c >> 5; q = c / 48;     // split
            int cc = c - q * 48;
            *(float4*)&xs[q * XQ_STR + cc * TILE_P + j * 4] = v;
        }
    }
    __syncthreads();

    // ---- phase 1: scores; split q over 48 channels; K via L1 (__ldg float4) ----
    {
        const int q = tid & 7;
        const int p = tid >> 3;
        const float* xq = xs + q * XQ_STR + p;
        const float* Kq = kvb + q * 48;

        float acc[8];
        #pragma unroll
        for (int k = 0; k < 8; k++) acc[k] = 0.f;

        #pragma unroll 3
        for (int i4 = 0; i4 < 12; i4++) {
            float x0 = xq[(i4 * 4 + 0) * TILE_P];
            float x1 = xq[(i4 * 4 + 1) * TILE_P];
            float x2 = xq[(i4 * 4 + 2) * TILE_P];
            float x3 = xq[(i4 * 4 + 3) * TILE_P];
            #pragma unroll
            for (int k = 0; k < 8; k++) {
                float4 kk = __ldg((const float4*)(Kq + k * E_DIM + i4 * 4));
                acc[k] += x0 * kk.x + x1 * kk.y + x2 * kk.z + x3 * kk.w;
            }
        }

        // butterfly over the 8 splits (aligned 8-lane groups)
        #pragma unroll
        for (int off = 1; off < 8; off <<= 1) {
            #pragma unroll
            for (int k = 0; k < 8; k++)
                acc[k] += __shfl_xor_sync(0xffffffffu, acc[k], off);
        }

        // softmax over k=8
        float mx = acc[0];
        #pragma unroll
        for (int k = 1; k < 8; k++) mx = fmaxf(mx, acc[k]);
        float sum = 0.f;
        #pragma unroll
        for (int k = 0; k < 8; k++) { acc[k] = __expf(acc[k] - mx); sum += acc[k]; }
        float inv = 1.0f / sum;
        if (q == 0) {
            float* ap = &attn[p * 8];
            *(float4*)(ap + 0) = make_float4(acc[0]*inv, acc[1]*inv, acc[2]*inv, acc[3]*inv);
            *(float4*)(ap + 4) = make_float4(acc[4]*inv, acc[5]*inv, acc[6]*inv, acc[7]*inv);
        }
    }
    __syncthreads();

    // ---- phase 2: out = x + attn @ V (coalesced stores) ----
    {
        const int q2 = tid / TILE_P;
        const int p2 = tid - q2 * TILE_P;

        float a[8];
        {
            const float* ap = &attn[p2 * 8];
            float4 u0 = *(const float4*)(ap + 0);
            float4 u1 = *(const float4*)(ap + 4);
            a[0]=u0.x; a[1]=u0.y; a[2]=u0.z; a[3]=u0.w;
            a[4]=u1.x; a[5]=u1.y; a[6]=u1.z; a[7]=u1.w;
        }

        const float* xq = xs + q2 * XQ_STR + p2;
        const float* Vq = kvb + C_DIM + q2 * 48;
        float* op = out + (size_t)n * C_DIM * HW + p0 + p2 + (size_t)(q2 * 48) * HW;

        #pragma unroll 3
        for (int i4 = 0; i4 < 12; i4++) {
            float o0 = xq[(i4 * 4 + 0) * TILE_P];
            float o1 = xq[(i4 * 4 + 1) * TILE_P];
            float o2 = xq[(i4 * 4 + 2) * TILE_P];
            float o3 = xq[(i4 * 4 + 3) * TILE_P];
            #pragma unroll
            for (int k = 0; k < 8; k++) {
                float4 vv = __ldg((const float4*)(Vq + k * E_DIM + i4 * 4));
                o0 += a[k] * vv.x; o1 += a[k] * vv.y;
                o2 += a[k] * vv.z; o3 += a[k] * vv.w;
            }
            op[(size_t)(i4 * 4 + 0) * HW] = o0;
            op[(size_t)(i4 * 4 + 1) * HW] = o1;
            op[(size_t)(i4 * 4 + 2) * HW] = o2;
            op[(size_t)(i4 * 4 + 3) * HW] = o3;
        }
    }
}

// ================= launch ======================================================
extern "C" void kernel_launch(void* const* d_in, const int* in_sizes, int n_in,
                              void* d_out, int out_size)
{
    const float* x  = (const float*)d_in[0];
    const float* gf = (const float*)d_in[1];
    const float* W  = (const float*)d_in[2];
    const float* b  = (const float*)d_in[3];
    float* out = (float*)d_out;

    kvp_kernel<<<dim3(E_DIM / BN, (N_B * M_DIM) / BM, NSPLIT), 256>>>(gf, W);
    kv_combine_kernel<<<(N_B * KV_N / 4) / 512, 512>>>(b);

    cudaFuncSetAttribute(attn_kernel, cudaFuncAttributeMaxDynamicSharedMemorySize, SM_BYTES);
    attn_kernel<<<dim3(HW / TILE_P, N_B), NTH, SM_BYTES>>>(x, out);
}

// round 5
// speedup vs baseline: 1.8445x; 1.5625x over previous
#include <cuda_runtime.h>
#include <math.h>

// Problem constants
#define N_B     32
#define C_DIM   384
#define HW      3136        // 56*56
#define M_DIM   8
#define D_MODEL 768
#define E_DIM   768         // 2*C
#define KV_N    (M_DIM * E_DIM)   // 6144 per batch

// ---------------- device scratch -----------------------------------------------
#define NSPLIT 8
__device__ __align__(16) float g_kvp[NSPLIT * N_B * KV_N]; // raw GEMM partials

// ================= Kernel 1: split-K GEMM partials =============================
#define BM 32
#define BN 64
#define BK 32
#define DSPL (D_MODEL / NSPLIT)   // 96

__global__ __launch_bounds__(256) void kvp_kernel(
    const float* __restrict__ gf,
    const float* __restrict__ W)
{
    __shared__ float As[BK][BM + 2];
    __shared__ float Bs[BK][BN + 4];

    const int tid = threadIdx.x;
    const int tx  = tid & 15;
    const int ty  = tid >> 4;
    const int eb  = blockIdx.x * BN;
    const int rb  = blockIdx.y * BM;
    const int s   = blockIdx.z;

    float acc[2][4];
    #pragma unroll
    for (int i = 0; i < 2; i++)
        #pragma unroll
        for (int j = 0; j < 4; j++) acc[i][j] = 0.f;

    for (int kb = s * DSPL; kb < (s + 1) * DSPL; kb += BK) {
        #pragma unroll
        for (int i = 0; i < 4; i++) {
            int idx = tid + i * 256;
            int r  = idx >> 5;
            int kk = idx & 31;
            As[kk][r] = gf[(size_t)(rb + r) * D_MODEL + kb + kk];
        }
        #pragma unroll
        for (int i = 0; i < 8; i++) {
            int idx = tid + i * 256;
            int e  = idx >> 5;
            int kk = idx & 31;
            Bs[kk][e] = W[(size_t)(eb + e) * D_MODEL + kb + kk];
        }
        __syncthreads();

        #pragma unroll
        for (int kk = 0; kk < BK; kk++) {
            float2 av = *(const float2*)&As[kk][ty * 2];
            float4 bv = *(const float4*)&Bs[kk][tx * 4];
            acc[0][0] += av.x * bv.x; acc[0][1] += av.x * bv.y;
            acc[0][2] += av.x * bv.z; acc[0][3] += av.x * bv.w;
            acc[1][0] += av.y * bv.x; acc[1][1] += av.y * bv.y;
            acc[1][2] += av.y * bv.z; acc[1][3] += av.y * bv.w;
        }
        __syncthreads();
    }

    float* dst = g_kvp + (size_t)s * (N_B * KV_N);
    #pragma unroll
    for (int r = 0; r < 2; r++) {
        float4 o = make_float4(acc[r][0], acc[r][1], acc[r][2], acc[r][3]);
        *(float4*)&dst[(size_t)(rb + ty * 2 + r) * E_DIM + eb + tx * 4] = o;
    }
}

// ================= Kernel 2: attention + residual ==============================
// x tile (384ch x 56px) in smem, read from HBM exactly once. K/V staged in smem
// (combined from split-K partials + bias + clip, padded q-stride-52 layout).
// Phase 1: tid = p*8+q (split q = 48 channels), butterfly reduce over lanes.
// Phase 2: tid = q2*56+p2, coalesced stores. 111.9 KB smem -> 2 CTAs/SM.
#define TILE_P  56
#define NTH     448
#define XQ_STR  2692                 // 48*56+4: phase-1 banks = 4q+p, conflict-free
#define KQ_STR  52                   // per-split K/V pad: banks 4*(13q+i), conflict-free
#define KROW    (8 * KQ_STR)         // 416 floats per k-row
#define OFF_KS  (8 * XQ_STR)         // 21536
#define OFF_VS  (OFF_KS + M_DIM * KROW)   // 24864
#define OFF_AT  (OFF_VS + M_DIM * KROW)   // 28192
#define SM_FLOATS (OFF_AT + TILE_P * 8)   // 28640
#define SM_BYTES  (SM_FLOATS * 4)         // 114560 -> 2 CTAs/SM

__global__ __launch_bounds__(NTH, 2) void attn_kernel(
    const float* __restrict__ x,
    const float* __restrict__ bias,
    float* __restrict__ out)
{
    extern __shared__ float sm[];
    float* xs   = sm;              // [q][c'][p]: q*2692 + c'*56 + p
    float* Ks   = sm + OFF_KS;     // [k][q*52 + c']
    float* Vs   = sm + OFF_VS;     // [k][q*52 + c']
    float* attn = sm + OFF_AT;     // [p][k]

    const int tid = threadIdx.x;
    const int n   = blockIdx.y;
    const int p0  = blockIdx.x * TILE_P;

    // ---- x tile load: 384 ch x 56 px (5376 float4, 12 per thread) ----
    {
        const float* xb = x + (size_t)n * C_DIM * HW + p0;
        #pragma unroll
        for (int t = 0; t < 12; t++) {
            int i = tid + t * NTH;
            int c = i / 14;                  // 14 float4 per channel row
            int j = i - c * 14;
            float4 v = *(const float4*)(xb + (size_t)c * HW + j * 4);
            int q  = c / 48;
            int cc = c - q * 48;
            *(float4*)&xs[q * XQ_STR + cc * TILE_P + j * 4] = v;
        }
    }

    // ---- stage K,V: combine 8 split partials + bias + clip (L2-hot) ----
    {
        const float4* pp = (const float4*)g_kvp;
        const float4* b4 = (const float4*)bias;
        const int base = n * (KV_N / 4);
        for (int i = tid; i < KV_N / 4; i += NTH) {   // 1536 float4
            float4 s0 = pp[0 * 49152 + base + i];
            float4 s1 = pp[1 * 49152 + base + i];
            float4 s2 = pp[2 * 49152 + base + i];
            float4 s3 = pp[3 * 49152 + base + i];
            float4 s4 = pp[4 * 49152 + base + i];
            float4 s5 = pp[5 * 49152 + base + i];
            float4 s6 = pp[6 * 49152 + base + i];
            float4 s7 = pp[7 * 49152 + base + i];
            int m = i / 192;
            int j = i - m * 192;
            float4 bb = b4[j];
            float4 o;
            o.x = fminf(fmaxf(s0.x+s1.x+s2.x+s3.x+s4.x+s5.x+s6.x+s7.x + bb.x, 0.f), 6.f);
            o.y = fminf(fmaxf(s0.y+s1.y+s2.y+s3.y+s4.y+s5.y+s6.y+s7.y + bb.y, 0.f), 6.f);
            o.z = fminf(fmaxf(s0.z+s1.z+s2.z+s3.z+s4.z+s5.z+s6.z+s7.z + bb.z, 0.f), 6.f);
            o.w = fminf(fmaxf(s0.w+s1.w+s2.w+s3.w+s4.w+s5.w+s6.w+s7.w + bb.w, 0.f), 6.f);
            int e = j * 4;
            if (e < C_DIM) {
                int q = e / 48, c = e - q * 48;
                *(float4*)&Ks[m * KROW + q * KQ_STR + c] = o;
            } else {
                int e2 = e - C_DIM;
                int q = e2 / 48, c = e2 - q * 48;
                *(float4*)&Vs[m * KROW + q * KQ_STR + c] = o;
            }
        }
    }
    __syncthreads();

    // ---- phase 1: scores; tid = p*8+q; K via conflict-free smem LDS.128 ----
    {
        const int q = tid & 7;
        const int p = tid >> 3;
        const float* xq = xs + q * XQ_STR + p;
        const float* Kq = Ks + q * KQ_STR;

        float acc[8];
        #pragma unroll
        for (int k = 0; k < 8; k++) acc[k] = 0.f;

        #pragma unroll 3
        for (int i4 = 0; i4 < 12; i4++) {
            float x0 = xq[(i4 * 4 + 0) * TILE_P];
            float x1 = xq[(i4 * 4 + 1) * TILE_P];
            float x2 = xq[(i4 * 4 + 2) * TILE_P];
            float x3 = xq[(i4 * 4 + 3) * TILE_P];
            #pragma unroll
            for (int k = 0; k < 8; k++) {
                float4 kk = *(const float4*)(Kq + k * KROW + i4 * 4);
                acc[k] += x0 * kk.x + x1 * kk.y + x2 * kk.z + x3 * kk.w;
            }
        }

        // butterfly over the 8 splits (aligned 8-lane groups)
        #pragma unroll
        for (int off = 1; off < 8; off <<= 1) {
            #pragma unroll
            for (int k = 0; k < 8; k++)
                acc[k] += __shfl_xor_sync(0xffffffffu, acc[k], off);
        }

        // softmax over k=8
        float mx = acc[0];
        #pragma unroll
        for (int k = 1; k < 8; k++) mx = fmaxf(mx, acc[k]);
        float sum = 0.f;
        #pragma unroll
        for (int k = 0; k < 8; k++) { acc[k] = __expf(acc[k] - mx); sum += acc[k]; }
        float inv = 1.0f / sum;
        if (q == 0) {
            float* ap = &attn[p * 8];
            *(float4*)(ap + 0) = make_float4(acc[0]*inv, acc[1]*inv, acc[2]*inv, acc[3]*inv);
            *(float4*)(ap + 4) = make_float4(acc[4]*inv, acc[5]*inv, acc[6]*inv, acc[7]*inv);
        }
    }
    __syncthreads();

    // ---- phase 2: out = x + attn @ V (coalesced stores) ----
    {
        const int q2 = tid / TILE_P;
        const int p2 = tid - q2 * TILE_P;

        float a[8];
        {
            const float* ap = &attn[p2 * 8];
            float4 u0 = *(const float4*)(ap + 0);
            float4 u1 = *(const float4*)(ap + 4);
            a[0]=u0.x; a[1]=u0.y; a[2]=u0.z; a[3]=u0.w;
            a[4]=u1.x; a[5]=u1.y; a[6]=u1.z; a[7]=u1.w;
        }

        const float* xq = xs + q2 * XQ_STR + p2;
        const float* Vq = Vs + q2 * KQ_STR;
        float* op = out + (size_t)n * C_DIM * HW + (size_t)(q2 * 48) * HW + p0 + p2;

        #pragma unroll 3
        for (int i4 = 0; i4 < 12; i4++) {
            float o0 = xq[(i4 * 4 + 0) * TILE_P];
            float o1 = xq[(i4 * 4 + 1) * TILE_P];
            float o2 = xq[(i4 * 4 + 2) * TILE_P];
            float o3 = xq[(i4 * 4 + 3) * TILE_P];
            #pragma unroll
            for (int k = 0; k < 8; k++) {
                float4 vv = *(const float4*)(Vq + k * KROW + i4 * 4);
                o0 += a[k] * vv.x; o1 += a[k] * vv.y;
                o2 += a[k] * vv.z; o3 += a[k] * vv.w;
            }
            op[(size_t)(i4 * 4 + 0) * HW] = o0;
            op[(size_t)(i4 * 4 + 1) * HW] = o1;
            op[(size_t)(i4 * 4 + 2) * HW] = o2;
            op[(size_t)(i4 * 4 + 3) * HW] = o3;
        }
    }
}

// ================= launch ======================================================
extern "C" void kernel_launch(void* const* d_in, const int* in_sizes, int n_in,
                              void* d_out, int out_size)
{
    const float* x  = (const float*)d_in[0];
    const float* gf = (const float*)d_in[1];
    const float* W  = (const float*)d_in[2];
    const float* b  = (const float*)d_in[3];
    float* out = (float*)d_out;

    kvp_kernel<<<dim3(E_DIM / BN, (N_B * M_DIM) / BM, NSPLIT), 256>>>(gf, W);

    cudaFuncSetAttribute(attn_kernel, cudaFuncAttributeMaxDynamicSharedMemorySize, SM_BYTES);
    attn_kernel<<<dim3(HW / TILE_P, N_B), NTH, SM_BYTES>>>(x, b, out);
}

// round 6
// speedup vs baseline: 2.1708x; 1.1769x over previous
#include <cuda_runtime.h>
#include <math.h>
#include <stdint.h>

// Problem constants
#define N_B     32
#define C_DIM   384
#define HW      3136        // 56*56
#define M_DIM   8
#define D_MODEL 768
#define E_DIM   768         // 2*C
#define KV_N    (M_DIM * E_DIM)   // 6144 per batch

// ---------------- device scratch -----------------------------------------------
#define NSPLIT 8
__device__ __align__(16) float g_kvp[NSPLIT * N_B * KV_N]; // raw GEMM partials

// ================= Kernel 1: split-K GEMM partials =============================
#define BM 32
#define BN 64
#define BK 32
#define DSPL (D_MODEL / NSPLIT)   // 96

__global__ __launch_bounds__(256) void kvp_kernel(
    const float* __restrict__ gf,
    const float* __restrict__ W)
{
    __shared__ float As[BK][BM + 2];
    __shared__ float Bs[BK][BN + 4];

    const int tid = threadIdx.x;
    const int tx  = tid & 15;
    const int ty  = tid >> 4;
    const int eb  = blockIdx.x * BN;
    const int rb  = blockIdx.y * BM;
    const int s   = blockIdx.z;

    float acc[2][4];
    #pragma unroll
    for (int i = 0; i < 2; i++)
        #pragma unroll
        for (int j = 0; j < 4; j++) acc[i][j] = 0.f;

    for (int kb = s * DSPL; kb < (s + 1) * DSPL; kb += BK) {
        #pragma unroll
        for (int i = 0; i < 4; i++) {
            int idx = tid + i * 256;
            int r  = idx >> 5;
            int kk = idx & 31;
            As[kk][r] = gf[(size_t)(rb + r) * D_MODEL + kb + kk];
        }
        #pragma unroll
        for (int i = 0; i < 8; i++) {
            int idx = tid + i * 256;
            int e  = idx >> 5;
            int kk = idx & 31;
            Bs[kk][e] = W[(size_t)(eb + e) * D_MODEL + kb + kk];
        }
        __syncthreads();

        #pragma unroll
        for (int kk = 0; kk < BK; kk++) {
            float2 av = *(const float2*)&As[kk][ty * 2];
            float4 bv = *(const float4*)&Bs[kk][tx * 4];
            acc[0][0] += av.x * bv.x; acc[0][1] += av.x * bv.y;
            acc[0][2] += av.x * bv.z; acc[0][3] += av.x * bv.w;
            acc[1][0] += av.y * bv.x; acc[1][1] += av.y * bv.y;
            acc[1][2] += av.y * bv.z; acc[1][3] += av.y * bv.w;
        }
        __syncthreads();
    }

    float* dst = g_kvp + (size_t)s * (N_B * KV_N);
    #pragma unroll
    for (int r = 0; r < 2; r++) {
        float4 o = make_float4(acc[r][0], acc[r][1], acc[r][2], acc[r][3]);
        *(float4*)&dst[(size_t)(rb + ty * 2 + r) * E_DIM + eb + tx * 4] = o;
    }
}

// ================= Kernel 2: persistent double-buffered attention ==============
#define TILE_P  56
#define NTH     448
#define NTILES  ((HW / TILE_P) * N_B)    // 1792

// xs buffer layout: [q 0..7][c' 0..47][px 0..55 +4 pad] -> q*2884 + c'*60 + px
#define QSTR   2884                       // 48*60+4 : q-chunks land on distinct banks
#define XBUF   (8 * QSTR)                 // 23072 words per buffer
#define KROW   416                        // K: [k][q*52 + c']  (52-pad per 48-ch block)
#define VROW   388                        // V: [k][c] plain, padded row
// smem word offsets
#define OFF_XS0  0
#define OFF_XS1  23072
#define OFF_KS   46144
#define OFF_VS   (OFF_KS + 8 * KROW)      // 49472
#define OFF_SC   (OFF_VS + 8 * VROW)      // 52576
#define OFF_AT   (OFF_SC + TILE_P * 8)    // 53024
#define SM_WORDS (OFF_AT + TILE_P * 8)    // 53472
#define SM_BYTES (SM_WORDS * 4)           // 213888

__device__ __forceinline__ void issue_tile_loads(
    const float* __restrict__ x, int t, float* buf, int tid)
{
    const int n  = t / 56;
    const int p0 = (t - n * 56) * TILE_P;
    const float* xb = x + (size_t)n * C_DIM * HW + p0;
    #pragma unroll
    for (int tt = 0; tt < 12; tt++) {
        int i  = tid + tt * NTH;          // float4 index, 0..5375
        int c  = i / 14;
        int j  = i - c * 14;
        int q  = c / 48;
        int cp = c - q * 48;
        uint32_t dst = (uint32_t)__cvta_generic_to_shared(buf + q * QSTR + cp * 60 + j * 4);
        const float* src = xb + (size_t)c * HW + j * 4;
        asm volatile("cp.async.cg.shared.global [%0], [%1], 16;\n" :: "r"(dst), "l"(src));
    }
    asm volatile("cp.async.commit_group;\n");
}

__device__ __forceinline__ void stage_kv(
    int n, const float* __restrict__ bias, float* Ks, float* Vs, int tid)
{
    const float4* pp = (const float4*)g_kvp;
    const float4* b4 = (const float4*)bias;
    const int base = n * (KV_N / 4);
    for (int i = tid; i < KV_N / 4; i += NTH) {   // 1536 float4
        float4 s0 = pp[0 * 49152 + base + i];
        float4 s1 = pp[1 * 49152 + base + i];
        float4 s2 = pp[2 * 49152 + base + i];
        float4 s3 = pp[3 * 49152 + base + i];
        float4 s4 = pp[4 * 49152 + base + i];
        float4 s5 = pp[5 * 49152 + base + i];
        float4 s6 = pp[6 * 49152 + base + i];
        float4 s7 = pp[7 * 49152 + base + i];
        int m = i / 192;
        int j = i - m * 192;
        float4 bb = b4[j];
        float4 o;
        o.x = fminf(fmaxf(s0.x+s1.x+s2.x+s3.x+s4.x+s5.x+s6.x+s7.x + bb.x, 0.f), 6.f);
        o.y = fminf(fmaxf(s0.y+s1.y+s2.y+s3.y+s4.y+s5.y+s6.y+s7.y + bb.y, 0.f), 6.f);
        o.z = fminf(fmaxf(s0.z+s1.z+s2.z+s3.z+s4.z+s5.z+s6.z+s7.z + bb.z, 0.f), 6.f);
        o.w = fminf(fmaxf(s0.w+s1.w+s2.w+s3.w+s4.w+s5.w+s6.w+s7.w + bb.w, 0.f), 6.f);
        int e = j * 4;
        if (e < C_DIM) {
            int q = e / 48, cp = e - q * 48;
            *(float4*)&Ks[m * KROW + q * 52 + cp] = o;
        } else {
            *(float4*)&Vs[m * VROW + (e - C_DIM)] = o;
        }
    }
}

__global__ __launch_bounds__(NTH, 1) void attn_persist(
    const float* __restrict__ x,
    const float* __restrict__ bias,
    float* __restrict__ out)
{
    extern __shared__ float sm[];
    float* xsb[2] = { sm + OFF_XS0, sm + OFF_XS1 };
    float* Ks     = sm + OFF_KS;
    float* Vs     = sm + OFF_VS;
    float* scores = sm + OFF_SC;
    float* attnw  = sm + OFF_AT;

    const int tid = threadIdx.x;
    const int G   = gridDim.x;
    const int cta = blockIdx.x;

    const int T = NTILES / G;
    const int R = NTILES % G;
    const int t0  = cta * T + (cta < R ? cta : R);
    const int cnt = T + (cta < R ? 1 : 0);
    if (cnt == 0) return;

    int curn = -1;

    // prologue: start loading tile t0 into buffer 0
    issue_tile_loads(x, t0, xsb[0], tid);

    for (int j = 0; j < cnt; j++) {
        const int t  = t0 + j;
        const int n  = t / 56;
        const int p0 = (t - n * 56) * TILE_P;
        float* buf = xsb[j & 1];

        // overlap: issue next tile's loads, then wait for current tile
        if (j + 1 < cnt) {
            issue_tile_loads(x, t + 1, xsb[(j + 1) & 1], tid);
            asm volatile("cp.async.wait_group 1;\n");
        } else {
            asm volatile("cp.async.wait_group 0;\n");
        }

        if (n != curn) {            // new batch: (re)stage K,V from split partials
            stage_kv(n, bias, Ks, Vs, tid);
            curn = n;
        }
        __syncthreads();            // buf ready + KV ready

        // ---------- phase 1: scores ----------
        {
            const int lane = tid & 31;
            const int pg   = tid >> 5;       // 0..13 (warp id) -> 4 pixels
            const int kg   = lane >> 3;      // 0..3  -> k pair
            const int q    = lane & 7;       // 0..7  -> 48-channel block
            const float* xq = buf + q * QSTR + pg * 4;
            const float* K0 = Ks + (kg * 2) * KROW + q * 52;
            const float* K1 = K0 + KROW;

            float acc0[4] = {0.f, 0.f, 0.f, 0.f};
            float acc1[4] = {0.f, 0.f, 0.f, 0.f};

            #pragma unroll
            for (int ch = 0; ch < 6; ch++) {         // chunks of 8 channels
                float4 ka0 = *(const float4*)(K0 + ch * 8);
                float4 kb0 = *(const float4*)(K0 + ch * 8 + 4);
                float4 ka1 = *(const float4*)(K1 + ch * 8);
                float4 kb1 = *(const float4*)(K1 + ch * 8 + 4);
                float k0v[8] = {ka0.x, ka0.y, ka0.z, ka0.w, kb0.x, kb0.y, kb0.z, kb0.w};
                float k1v[8] = {ka1.x, ka1.y, ka1.z, ka1.w, kb1.x, kb1.y, kb1.z, kb1.w};
                #pragma unroll
                for (int cc = 0; cc < 8; cc++) {
                    float4 xv = *(const float4*)(xq + (ch * 8 + cc) * 60);
                    acc0[0] += xv.x * k0v[cc]; acc0[1] += xv.y * k0v[cc];
                    acc0[2] += xv.z * k0v[cc]; acc0[3] += xv.w * k0v[cc];
                    acc1[0] += xv.x * k1v[cc]; acc1[1] += xv.y * k1v[cc];
                    acc1[2] += xv.z * k1v[cc]; acc1[3] += xv.w * k1v[cc];
                }
            }
            // reduce over the 8 channel-blocks (lanes within each kg octet)
            #pragma unroll
            for (int off = 1; off < 8; off <<= 1) {
                #pragma unroll
                for (int pp2 = 0; pp2 < 4; pp2++) {
                    acc0[pp2] += __shfl_xor_sync(0xffffffffu, acc0[pp2], off);
                    acc1[pp2] += __shfl_xor_sync(0xffffffffu, acc1[pp2], off);
                }
            }
            if (q == 0) {
                #pragma unroll
                for (int pp2 = 0; pp2 < 4; pp2++) {
                    int px = pg * 4 + pp2;
                    *(float2*)&scores[px * 8 + kg * 2] = make_float2(acc0[pp2], acc1[pp2]);
                }
            }
        }
        __syncthreads();

        // ---------- softmax over k=8 ----------
        if (tid < TILE_P) {
            float4 u0 = *(const float4*)&scores[tid * 8];
            float4 u1 = *(const float4*)&scores[tid * 8 + 4];
            float s[8] = {u0.x, u0.y, u0.z, u0.w, u1.x, u1.y, u1.z, u1.w};
            float mx = s[0];
            #pragma unroll
            for (int k = 1; k < 8; k++) mx = fmaxf(mx, s[k]);
            float sum = 0.f;
            #pragma unroll
            for (int k = 0; k < 8; k++) { s[k] = __expf(s[k] - mx); sum += s[k]; }
            float inv = 1.0f / sum;
            *(float4*)&attnw[tid * 8]     = make_float4(s[0]*inv, s[1]*inv, s[2]*inv, s[3]*inv);
            *(float4*)&attnw[tid * 8 + 4] = make_float4(s[4]*inv, s[5]*inv, s[6]*inv, s[7]*inv);
        }
        __syncthreads();

        // ---------- phase 2: out = x + attn @ V ----------
        {
            const int cg = tid / 14;         // 0..31 -> 12 channels
            const int pg = tid - cg * 14;    // 0..13 -> 4 pixels

            float a[4][8];
            #pragma unroll
            for (int pp2 = 0; pp2 < 4; pp2++) {
                float4 u0 = *(const float4*)&attnw[(pg * 4 + pp2) * 8];
                float4 u1 = *(const float4*)&attnw[(pg * 4 + pp2) * 8 + 4];
                a[pp2][0] = u0.x; a[pp2][1] = u0.y; a[pp2][2] = u0.z; a[pp2][3] = u0.w;
                a[pp2][4] = u1.x; a[pp2][5] = u1.y; a[pp2][6] = u1.z; a[pp2][7] = u1.w;
            }

            float* op = out + (size_t)n * C_DIM * HW + p0 + pg * 4;
            #pragma unroll 3
            for (int jj = 0; jj < 12; jj++) {
                int c  = cg * 12 + jj;
                int q  = c / 48;
                int cp = c - q * 48;
                float4 xv = *(const float4*)(buf + q * QSTR + cp * 60 + pg * 4);
                float o0 = xv.x, o1 = xv.y, o2 = xv.z, o3 = xv.w;
                const float* Vc = Vs + c;
                #pragma unroll
                for (int k = 0; k < 8; k++) {
                    float vk = Vc[k * VROW];
                    o0 += a[0][k] * vk; o1 += a[1][k] * vk;
                    o2 += a[2][k] * vk; o3 += a[3][k] * vk;
                }
                *(float4*)(op + (size_t)c * HW) = make_float4(o0, o1, o2, o3);
            }
        }
        __syncthreads();   // all reads of buf done before it is overwritten
    }
}

// ================= launch ======================================================
extern "C" void kernel_launch(void* const* d_in, const int* in_sizes, int n_in,
                              void* d_out, int out_size)
{
    const float* x  = (const float*)d_in[0];
    const float* gf = (const float*)d_in[1];
    const float* W  = (const float*)d_in[2];
    const float* b  = (const float*)d_in[3];
    float* out = (float*)d_out;

    kvp_kernel<<<dim3(E_DIM / BN, (N_B * M_DIM) / BM, NSPLIT), 256>>>(gf, W);

    int nsm = 0;
    cudaDeviceGetAttribute(&nsm, cudaDevAttrMultiProcessorCount, 0);
    if (nsm <= 0) nsm = 148;
    if (nsm > NTILES) nsm = NTILES;

    cudaFuncSetAttribute(attn_persist, cudaFuncAttributeMaxDynamicSharedMemorySize, SM_BYTES);
    attn_persist<<<nsm, NTH, SM_BYTES>>>(x, b, out);
}